// round 12
// baseline (speedup 1.0000x reference)
#include <cuda_runtime.h>
#include <cuda_fp16.h>
#include <mma.h>
#include <math.h>
#include <stdint.h>

using namespace nvcuda;

// Problem constants
#define B_    128
#define D_    2048
#define C_    16522
#define KNN_  6
#define BM    128
#define KC    32             // f32 K-elements per chunk
#define LDA   40             // KC + 8 pad
#define LDE   136            // epilogue f32 row stride (128 + 8)
#define KHALF 1024           // K per warp-group
#define NCHG  (KHALF / KC)   // 32 chunks per group
#define NTILE 130            // ceil(C_/128)
#define NTHR  512

// Per-tile softmax partials
static __device__ float g_pm[B_ * NTILE];
static __device__ float g_ps[B_ * NTILE];
static __device__ float g_tv6[B_ * NTILE * KNN_];
static __device__ int   g_ti6[B_ * NTILE * KNN_];
static __device__ float g_vlab[B_];
static __device__ float g_rowloss[B_];
static __device__ int   g_done = 0;

#define STG_HALFS (BM * LDA)
#define SMEM_DYN  (2 * 128 * LDE * 4)     // 139264

static __device__ __forceinline__ __half* SP(char* base, int g, int st, int mat) {
    return (__half*)base + ((g * 3 + st) * 2 + mat) * STG_HALFS;
}
static __device__ __forceinline__ void gbar(int g) {
    asm volatile("bar.sync %0, 256;" :: "r"(g + 1) : "memory");
}

// ---------------------------------------------------------------------------
// GEMM: fp16 HMMA (logits = X·Emᵀ x20) + per-tile partial softmax/top-6.
// R9 skeleton, copy and EMA removed (copy -> CE memcpy, EMA -> finalize).
// ---------------------------------------------------------------------------
__global__ __launch_bounds__(NTHR, 1) void gemm_part(const float* __restrict__ X,
                                                     const float* __restrict__ Em,
                                                     const int* __restrict__ label) {
    extern __shared__ char smraw[];

    const int tid  = threadIdx.x;
    const int wid  = tid >> 5;
    const int grp  = wid >> 3;
    const int gtid = tid & 255;
    const int w8   = wid & 7;
    const int bt   = blockIdx.x;
    const int c0   = bt * BM;
    const int wm   = (w8 & 3) * 32;
    const int wn   = (w8 >> 2) * 64;
    const int kbase = grp * KHALF;

    wmma::fragment<wmma::accumulator, 16, 16, 16, float> acc[2][4];
    #pragma unroll
    for (int i = 0; i < 2; i++)
        #pragma unroll
        for (int j = 0; j < 4; j++) wmma::fill_fragment(acc[i][j], 0.0f);

    float4 pf[8];

    auto ldchunk = [&](int chunk) {
        const int k0 = kbase + chunk * KC;
        #pragma unroll
        for (int t = 0; t < 8; t++) {
            const int g   = gtid + t * 256;
            const int mat = g >> 10;
            const int idx = g & 1023;
            const int row = idx >> 3;
            const int q   = idx & 7;
            if (mat == 0) {
                const int c = c0 + row;
                pf[t] = (c < C_) ? __ldcs((const float4*)(Em + (long long)c * D_ + k0 + q * 4))
                                 : make_float4(0.f, 0.f, 0.f, 0.f);
            } else {
                pf[t] = *(const float4*)(X + (long long)row * D_ + k0 + q * 4);
            }
        }
    };

    auto stchunk = [&](int st) {
        __half* Ab = SP(smraw, grp, st, 0);
        __half* Bb = SP(smraw, grp, st, 1);
        #pragma unroll
        for (int t = 0; t < 8; t++) {
            const int g   = gtid + t * 256;
            const int mat = g >> 10;
            const int idx = g & 1023;
            const int row = idx >> 3;
            const int q   = idx & 7;
            float4 f = pf[t];
            __half2 h0 = __float22half2_rn(make_float2(f.x, f.y));
            __half2 h1 = __float22half2_rn(make_float2(f.z, f.w));
            __half* hb = mat ? Bb : Ab;
            const int so = row * LDA + q * 4;
            *(__half2*)(hb + so)     = h0;
            *(__half2*)(hb + so + 2) = h1;
        }
    };

    ldchunk(0); stchunk(0);
    ldchunk(1); stchunk(1);
    gbar(grp);

    for (int s = 0; s < NCHG; s++) {
        const int st = s % 3;
        const bool more = (s + 2 < NCHG);
        if (more) ldchunk(s + 2);

        __half* Ab = SP(smraw, grp, st, 0);
        __half* Bb = SP(smraw, grp, st, 1);
        #pragma unroll
        for (int kk = 0; kk < KC; kk += 16) {
            wmma::fragment<wmma::matrix_a, 16, 16, 16, __half, wmma::row_major> af[2];
            wmma::fragment<wmma::matrix_b, 16, 16, 16, __half, wmma::col_major> bf[4];
            #pragma unroll
            for (int i = 0; i < 2; i++)
                wmma::load_matrix_sync(af[i], Ab + (wm + i * 16) * LDA + kk, LDA);
            #pragma unroll
            for (int j = 0; j < 4; j++)
                wmma::load_matrix_sync(bf[j], Bb + (wn + j * 16) * LDA + kk, LDA);
            #pragma unroll
            for (int i = 0; i < 2; i++)
                #pragma unroll
                for (int j = 0; j < 4; j++)
                    wmma::mma_sync(acc[i][j], af[i], bf[j], acc[i][j]);
        }

        if (more) stchunk((s + 2) % 3);
        gbar(grp);
    }

    // ============== sum split-K accumulators; partial softmax ==============
    __shared__ int   lab[B_];
    __shared__ float tvv[NTHR][KNN_];
    __shared__ int   tii[NTHR][KNN_];

    if (tid < B_) lab[tid] = label[tid];
    __syncthreads();

    float* LT0 = (float*)smraw;
    float* LT1 = LT0 + 128 * LDE;
    float* LTg = grp ? LT1 : LT0;
    #pragma unroll
    for (int i = 0; i < 2; i++)
        #pragma unroll
        for (int j = 0; j < 4; j++)
            wmma::store_matrix_sync(LTg + (wn + j * 16) * LDE + (wm + i * 16),
                                    acc[i][j], LDE, wmma::mem_col_major);
    __syncthreads();

    {
        const int n   = tid >> 2;
        const int seg = tid & 3;
        const float* s0 = LT0 + n * LDE + seg * 32;
        const float* s1 = LT1 + n * LDE + seg * 32;

        float v[32];
        #pragma unroll
        for (int q = 0; q < 8; q++) {
            float4 f0 = *(const float4*)(s0 + q * 4);
            float4 f1 = *(const float4*)(s1 + q * 4);
            v[q * 4 + 0] = (f0.x + f1.x) * 20.0f;
            v[q * 4 + 1] = (f0.y + f1.y) * 20.0f;
            v[q * 4 + 2] = (f0.z + f1.z) * 20.0f;
            v[q * 4 + 3] = (f0.w + f1.w) * 20.0f;
        }
        if (c0 + BM > C_) {
            #pragma unroll
            for (int k = 0; k < 32; k++)
                if (c0 + seg * 32 + k >= C_) v[k] = -INFINITY;
        }

        float mt = -INFINITY;
        #pragma unroll
        for (int k = 0; k < 32; k++) mt = fmaxf(mt, v[k]);

        float st_ = 0.f;
        if (mt > -INFINITY) {
            #pragma unroll
            for (int k = 0; k < 32; k += 2) {
                __half2 e = h2exp(__floats2half2_rn(v[k] - mt, v[k + 1] - mt));
                float2 ef = __half22float2(e);
                st_ += ef.x + ef.y;
            }
        }

        float tv[KNN_]; int ti[KNN_];
        #pragma unroll
        for (int j = 0; j < KNN_; j++) { tv[j] = -INFINITY; ti[j] = -1; }
        #pragma unroll
        for (int k = 0; k < 32; k++) {
            float x = v[k];
            if (x > tv[KNN_ - 1]) {
                int p = KNN_ - 1;
                while (p > 0 && x > tv[p - 1]) { tv[p] = tv[p - 1]; ti[p] = ti[p - 1]; p--; }
                tv[p] = x; ti[p] = seg * 32 + k;
            }
        }

        float m_ = mt, s_ = st_;
        #pragma unroll
        for (int o = 1; o <= 2; o <<= 1) {
            float mo = __shfl_xor_sync(0xffffffffu, m_, o);
            float so = __shfl_xor_sync(0xffffffffu, s_, o);
            float mm = fmaxf(m_, mo);
            float a  = (s_ > 0.f) ? s_ * __expf(m_ - mm) : 0.f;
            float b2 = (so > 0.f) ? so * __expf(mo - mm) : 0.f;
            m_ = mm; s_ = a + b2;
        }

        #pragma unroll
        for (int j = 0; j < KNN_; j++) { tvv[tid][j] = tv[j]; tii[tid][j] = ti[j]; }
        __syncwarp();

        if (seg == 0) {
            int p[4] = {0, 0, 0, 0};
            float otv[KNN_]; int oti[KNN_];
            #pragma unroll
            for (int r = 0; r < KNN_; r++) {
                float bv = -INFINITY; int bs = -1;
                #pragma unroll
                for (int q = 0; q < 4; q++) {
                    if (p[q] < KNN_) {
                        float cv_ = tvv[tid + q][p[q]];
                        if (cv_ > bv) { bv = cv_; bs = q; }
                    }
                }
                otv[r] = bv;
                oti[r] = (bs >= 0) ? c0 + tii[tid + bs][p[bs]] : -1;
                if (bs >= 0) p[bs]++;
            }
            const int o = n * NTILE + bt;
            g_pm[o] = m_;
            g_ps[o] = s_;
            #pragma unroll
            for (int j = 0; j < KNN_; j++) { g_tv6[o * KNN_ + j] = otv[j]; g_ti6[o * KNN_ + j] = oti[j]; }

            const int y = lab[n];
            if (y >= c0 && y < c0 + BM)
                g_vlab[n] = (LT0[n * LDE + (y - c0)] + LT1[n * LDE + (y - c0)]) * 20.0f;
        }
    }
}

// ---------------------------------------------------------------------------
// Finalize: combine (R11 v2) + EMA update + mean loss.
// 128 blocks x 128 thr; block b = batch row b (and EMA chain if b is head).
// Runs AFTER the CE memcpy join, so EMA rows overwrite the copied rows.
// ---------------------------------------------------------------------------
__global__ __launch_bounds__(128) void finalize_kernel(const float* __restrict__ X,
                                                       const int* __restrict__ label,
                                                       const float* __restrict__ Em,
                                                       const int* __restrict__ epoch_p,
                                                       float* __restrict__ out1,
                                                       float* __restrict__ loss_out) {
    const int tid  = threadIdx.x;
    const int lane = tid & 31;
    const int wrp  = tid >> 5;
    const int b    = blockIdx.x;

    __shared__ int lab[B_];
    if (tid < B_) lab[tid] = label[tid];
    __syncthreads();

    // ---------------- combine ----------------
    float m = -INFINITY, s = 0.f;
    float tv[KNN_]; int ti[KNN_];
    #pragma unroll
    for (int j = 0; j < KNN_; j++) { tv[j] = -INFINITY; ti[j] = -1; }

    for (int t = tid; t < NTILE; t += 128) {
        const int o = b * NTILE + t;
        float mo = g_pm[o], so = g_ps[o];
        float mm = fmaxf(m, mo);
        float a  = (s  > 0.f) ? s  * __expf(m  - mm) : 0.f;
        float c2 = (so > 0.f) ? so * __expf(mo - mm) : 0.f;
        m = mm; s = a + c2;
        #pragma unroll
        for (int j = 0; j < KNN_; j++) {
            float x = g_tv6[o * KNN_ + j];
            if (x > tv[KNN_ - 1]) {
                int xi = g_ti6[o * KNN_ + j];
                int p = KNN_ - 1;
                while (p > 0 && x > tv[p - 1]) { tv[p] = tv[p - 1]; ti[p] = ti[p - 1]; p--; }
                tv[p] = x; ti[p] = xi;
            } else break;
        }
    }

    #pragma unroll
    for (int o = 16; o > 0; o >>= 1) {
        float mo = __shfl_xor_sync(0xffffffffu, m, o);
        float so = __shfl_xor_sync(0xffffffffu, s, o);
        float mm = fmaxf(m, mo);
        float a  = (s  > 0.f) ? s  * __expf(m  - mm) : 0.f;
        float c2 = (so > 0.f) ? so * __expf(mo - mm) : 0.f;
        m = mm; s = a + c2;
    }

    float wtv[KNN_]; int wti[KNN_];
    {
        int p = 0;
        #pragma unroll
        for (int r = 0; r < KNN_; r++) {
            float cand = (p < KNN_) ? tv[p] : -INFINITY;
            int   cidx = (p < KNN_) ? ti[p] : -1;
            float bv = cand; int bl = lane;
            #pragma unroll
            for (int o = 16; o > 0; o >>= 1) {
                float ov = __shfl_xor_sync(0xffffffffu, bv, o);
                int   ol = __shfl_xor_sync(0xffffffffu, bl, o);
                if (ov > bv || (ov == bv && ol < bl)) { bv = ov; bl = ol; }
            }
            int widx = __shfl_sync(0xffffffffu, cidx, bl);
            if (lane == bl) p++;
            wtv[r] = bv; wti[r] = widx;
        }
    }

    __shared__ float smm[4], sms[4];
    __shared__ float swv[4][KNN_];
    __shared__ int   swi[4][KNN_];
    if (lane == 0) { smm[wrp] = m; sms[wrp] = s; }
    if (lane < KNN_) { swv[wrp][lane] = wtv[lane]; swi[wrp][lane] = wti[lane]; }
    __syncthreads();

    if (wrp == 0) {
        float fm = smm[0], fs = sms[0];
        #pragma unroll
        for (int w = 1; w < 4; w++) {
            float mo = smm[w], so = sms[w];
            float mm2 = fmaxf(fm, mo);
            float a  = (fs > 0.f) ? fs * __expf(fm - mm2) : 0.f;
            float c2 = (so > 0.f) ? so * __expf(mo - mm2) : 0.f;
            fm = mm2; fs = a + c2;
        }
        const float LSE = fm + logf(fs);

        float cand = (lane < 24) ? swv[lane / KNN_][lane % KNN_] : -INFINITY;
        int   cidx = (lane < 24) ? swi[lane / KNN_][lane % KNN_] : -1;

        const int y = lab[b];
        float sum6 = 0.f;
        int   in = 0;
        #pragma unroll
        for (int r = 0; r < KNN_; r++) {
            float bv = cand; int bl = lane;
            #pragma unroll
            for (int o = 16; o > 0; o >>= 1) {
                float ov = __shfl_xor_sync(0xffffffffu, bv, o);
                int   ol = __shfl_xor_sync(0xffffffffu, bl, o);
                if (ov > bv || (ov == bv && ol < bl)) { bv = ov; bl = ol; }
            }
            int widx = __shfl_sync(0xffffffffu, cidx, bl);
            if (lane == bl) cand = -INFINITY;
            sum6 += (LSE - bv);
            if (widx == y) in = 1;
        }

        if (lane == 0) {
            float ll = LSE - g_vlab[b];
            g_rowloss[b] = 2.f * sum6 + (3.f - 2.f * (float)in) * ll;
        }
    }
    __syncthreads();

    // ---------------- EMA update (block b = chain head b) ----------------
    {
        const int y = lab[b];
        bool head = true;
        for (int j = 0; j < b; j++)
            if (lab[j] == y) { head = false; break; }

        if (head) {
            const float alpha = 0.01f * (float)epoch_p[0];
            __shared__ float red[5];

            float r[16];
            #pragma unroll
            for (int k = 0; k < 16; k++) r[k] = Em[(long long)y * D_ + k * 128 + tid];

            for (int i = b; i < B_; i++) {
                if (lab[i] != y) continue;
                float sq = 0.f;
                #pragma unroll
                for (int k = 0; k < 16; k++) {
                    r[k] = alpha * r[k] + (1.f - alpha) * X[i * D_ + k * 128 + tid];
                    sq = fmaf(r[k], r[k], sq);
                }
                #pragma unroll
                for (int o = 16; o > 0; o >>= 1) sq += __shfl_xor_sync(0xffffffffu, sq, o);
                if (lane == 0) red[wrp] = sq;
                __syncthreads();
                if (tid == 0) red[4] = red[0] + red[1] + red[2] + red[3];
                __syncthreads();
                float inv = rsqrtf(red[4]);
                __syncthreads();
                #pragma unroll
                for (int k = 0; k < 16; k++) r[k] *= inv;
            }

            #pragma unroll
            for (int k = 0; k < 16; k++) out1[(long long)y * D_ + k * 128 + tid] = r[k];
        }
    }

    // ---------------- last block: mean loss ----------------
    __shared__ int is_last;
    __syncthreads();
    if (tid == 0) {
        __threadfence();
        is_last = (atomicAdd(&g_done, 1) == B_ - 1);
    }
    __syncthreads();
    if (is_last && tid < 32) {
        float accv = 0.f;
        #pragma unroll
        for (int k = 0; k < 4; k++) accv += g_rowloss[tid + k * 32];
        #pragma unroll
        for (int o = 16; o > 0; o >>= 1) accv += __shfl_xor_sync(0xffffffffu, accv, o);
        if (tid == 0) {
            loss_out[0] = accv / (float)B_;
            g_done = 0;
        }
    }
}

// ---------------------------------------------------------------------------
// Launch: fork CE memcpy (em copy) || gemm, join, finalize.
// ---------------------------------------------------------------------------
extern "C" void kernel_launch(void* const* d_in, const int* in_sizes, int n_in,
                              void* d_out, int out_size) {
    const float* X     = (const float*)d_in[0];  // [128, 2048] f32
    const int*   label = (const int*)  d_in[1];  // [128] i32
    const float* Em    = (const float*)d_in[2];  // [16522, 2048] f32
    const int*   epoch = (const int*)  d_in[3];  // scalar

    float* out = (float*)d_out;                  // [0]=loss, [1..]=em_new

    static cudaStream_t s2 = nullptr;
    static cudaEvent_t  evF = nullptr, evJ = nullptr;
    if (!s2) {
        cudaStreamCreateWithFlags(&s2, cudaStreamNonBlocking);
        cudaEventCreateWithFlags(&evF, cudaEventDisableTiming);
        cudaEventCreateWithFlags(&evJ, cudaEventDisableTiming);
    }

    cudaFuncSetAttribute(gemm_part, cudaFuncAttributeMaxDynamicSharedMemorySize, SMEM_DYN);

    // fork: copy-engine em -> out[1..] runs concurrently with the GEMM
    cudaEventRecord(evF, 0);
    cudaStreamWaitEvent(s2, evF, 0);
    cudaMemcpyAsync(out + 1, Em, (size_t)C_ * D_ * sizeof(float),
                    cudaMemcpyDeviceToDevice, s2);
    cudaEventRecord(evJ, s2);

    gemm_part<<<NTILE, NTHR, SMEM_DYN>>>(X, Em, label);

    // join: EMA writes in finalize must land after the bulk copy
    cudaStreamWaitEvent(0, evJ, 0);
    finalize_kernel<<<B_, 128>>>(X, label, Em, epoch, out + 1, out);
}

// round 13
// speedup vs baseline: 1.4400x; 1.4400x over previous
#include <cuda_runtime.h>
#include <cuda_fp16.h>
#include <mma.h>
#include <math.h>
#include <stdint.h>

using namespace nvcuda;

// Problem constants
#define B_    128
#define D_    2048
#define C_    16522
#define KNN_  6
#define BM    128
#define KC    32             // f32 K-elements per chunk
#define LDA   40             // KC + 8 pad
#define LDE   136            // epilogue f32 row stride (128 + 8)
#define KHALF 1024           // K per warp-group
#define NCHG  (KHALF / KC)   // 32 chunks per group
#define NST   4              // staging stages (prefetch distance 2 iterations)
#define NTILE 130            // ceil(C_/128)
#define NTHR  512

// Per-tile softmax partials
static __device__ float g_pm[B_ * NTILE];
static __device__ float g_ps[B_ * NTILE];
static __device__ float g_tv6[B_ * NTILE * KNN_];
static __device__ int   g_ti6[B_ * NTILE * KNN_];
static __device__ float g_vlab[B_];
static __device__ float g_rowloss[B_];
static __device__ int   g_done = 0;

#define STG_HALFS (BM * LDA)
// staging: 2 groups x 4 stages x 2 mats x 10240 B = 163840 B
// epilogue reuse: 2 x 128 x LDE x 4 = 139264 B
#define SMEM_DYN  (2 * NST * 2 * STG_HALFS * 2)   // 163840

static __device__ __forceinline__ __half* SP(char* base, int g, int st, int mat) {
    return (__half*)base + ((g * NST + st) * 2 + mat) * STG_HALFS;
}
static __device__ __forceinline__ void gbar(int g) {
    asm volatile("bar.sync %0, 256;" :: "r"(g + 1) : "memory");
}

// ---------------------------------------------------------------------------
// Fused: fp16 HMMA GEMM (logits = X·Emᵀ x20) + em->out copy + partial
// softmax/top-6 + EMA update. Two split-K warp-group pipelines per CTA.
// v13: pf registers carry a full iteration (st before ld), 4 stages —
// doubles the LDG latency-hiding window vs R11.
// ---------------------------------------------------------------------------
__global__ __launch_bounds__(NTHR, 1) void gemm_fused(const float* __restrict__ X,
                                                      const float* __restrict__ Em,
                                                      const int* __restrict__ label,
                                                      const int* __restrict__ epoch_p,
                                                      float* __restrict__ out1) {
    extern __shared__ char smraw[];

    const int tid  = threadIdx.x;
    const int wid  = tid >> 5;
    const int grp  = wid >> 3;         // warp-group 0 or 1
    const int gtid = tid & 255;
    const int w8   = wid & 7;
    const int bt   = blockIdx.x;
    const int c0   = bt * BM;
    const int wm   = (w8 & 3) * 32;
    const int wn   = (w8 >> 2) * 64;
    const int kbase = grp * KHALF;

    wmma::fragment<wmma::accumulator, 16, 16, 16, float> acc[2][4];
    #pragma unroll
    for (int i = 0; i < 2; i++)
        #pragma unroll
        for (int j = 0; j < 4; j++) wmma::fill_fragment(acc[i][j], 0.0f);

    float4 pf[8];

    auto ldchunk = [&](int chunk) {
        const int k0 = kbase + chunk * KC;
        #pragma unroll
        for (int t = 0; t < 8; t++) {
            const int g   = gtid + t * 256;
            const int mat = g >> 10;
            const int idx = g & 1023;
            const int row = idx >> 3;
            const int q   = idx & 7;
            if (mat == 0) {
                const int c = c0 + row;
                pf[t] = (c < C_) ? __ldcs((const float4*)(Em + (long long)c * D_ + k0 + q * 4))
                                 : make_float4(0.f, 0.f, 0.f, 0.f);
            } else {
                pf[t] = *(const float4*)(X + (long long)row * D_ + k0 + q * 4);
            }
        }
    };

    auto stchunk = [&](int chunk, int st) {
        const int k0 = kbase + chunk * KC;
        __half* Ab = SP(smraw, grp, st, 0);
        __half* Bb = SP(smraw, grp, st, 1);
        #pragma unroll
        for (int t = 0; t < 8; t++) {
            const int g   = gtid + t * 256;
            const int mat = g >> 10;
            const int idx = g & 1023;
            const int row = idx >> 3;
            const int q   = idx & 7;
            float4 f = pf[t];
            __half2 h0 = __float22half2_rn(make_float2(f.x, f.y));
            __half2 h1 = __float22half2_rn(make_float2(f.z, f.w));
            __half* hb = mat ? Bb : Ab;
            const int so = row * LDA + q * 4;
            *(__half2*)(hb + so)     = h0;
            *(__half2*)(hb + so + 2) = h1;
            if (mat == 0 && c0 + row < C_) {
                float* o = out1 + (long long)(c0 + row) * D_ + k0 + q * 4;
                __stcs(o + 0, f.x); __stcs(o + 1, f.y);
                __stcs(o + 2, f.z); __stcs(o + 3, f.w);
            }
        }
    };

    // prologue: stages 0,1 filled; pf holds chunk 2
    ldchunk(0); stchunk(0, 0);
    ldchunk(1); stchunk(1, 1);
    ldchunk(2);
    gbar(grp);

    for (int s = 0; s < NCHG; s++) {
        const int st = s % NST;
        if (s + 2 < NCHG) stchunk(s + 2, (s + 2) % NST);   // pf loaded last iter
        if (s + 3 < NCHG) ldchunk(s + 3);                  // refill pf (full-iter window)

        __half* Ab = SP(smraw, grp, st, 0);
        __half* Bb = SP(smraw, grp, st, 1);
        #pragma unroll
        for (int kk = 0; kk < KC; kk += 16) {
            wmma::fragment<wmma::matrix_a, 16, 16, 16, __half, wmma::row_major> af[2];
            wmma::fragment<wmma::matrix_b, 16, 16, 16, __half, wmma::col_major> bf[4];
            #pragma unroll
            for (int i = 0; i < 2; i++)
                wmma::load_matrix_sync(af[i], Ab + (wm + i * 16) * LDA + kk, LDA);
            #pragma unroll
            for (int j = 0; j < 4; j++)
                wmma::load_matrix_sync(bf[j], Bb + (wn + j * 16) * LDA + kk, LDA);
            #pragma unroll
            for (int i = 0; i < 2; i++)
                #pragma unroll
                for (int j = 0; j < 4; j++)
                    wmma::mma_sync(acc[i][j], af[i], bf[j], acc[i][j]);
        }

        gbar(grp);
    }

    // ============== sum the two split-K accumulator sets ==============
    __shared__ int   lab[B_];
    __shared__ float red[17];
    __shared__ float tvv[NTHR][KNN_];
    __shared__ int   tii[NTHR][KNN_];

    if (tid < B_) lab[tid] = label[tid];
    __syncthreads();

    float* LT0 = (float*)smraw;
    float* LT1 = LT0 + 128 * LDE;
    float* LTg = grp ? LT1 : LT0;
    #pragma unroll
    for (int i = 0; i < 2; i++)
        #pragma unroll
        for (int j = 0; j < 4; j++)
            wmma::store_matrix_sync(LTg + (wn + j * 16) * LDE + (wm + i * 16),
                                    acc[i][j], LDE, wmma::mem_col_major);
    __syncthreads();

    {
        const int n   = tid >> 2;
        const int seg = tid & 3;
        const float* s0 = LT0 + n * LDE + seg * 32;
        const float* s1 = LT1 + n * LDE + seg * 32;

        float v[32];
        #pragma unroll
        for (int q = 0; q < 8; q++) {
            float4 f0 = *(const float4*)(s0 + q * 4);
            float4 f1 = *(const float4*)(s1 + q * 4);
            v[q * 4 + 0] = (f0.x + f1.x) * 20.0f;
            v[q * 4 + 1] = (f0.y + f1.y) * 20.0f;
            v[q * 4 + 2] = (f0.z + f1.z) * 20.0f;
            v[q * 4 + 3] = (f0.w + f1.w) * 20.0f;
        }
        if (c0 + BM > C_) {
            #pragma unroll
            for (int k = 0; k < 32; k++)
                if (c0 + seg * 32 + k >= C_) v[k] = -INFINITY;
        }

        float mt = -INFINITY;
        #pragma unroll
        for (int k = 0; k < 32; k++) mt = fmaxf(mt, v[k]);

        float st_ = 0.f;
        if (mt > -INFINITY) {
            #pragma unroll
            for (int k = 0; k < 32; k += 2) {
                __half2 e = h2exp(__floats2half2_rn(v[k] - mt, v[k + 1] - mt));
                float2 ef = __half22float2(e);
                st_ += ef.x + ef.y;
            }
        }

        float tv[KNN_]; int ti[KNN_];
        #pragma unroll
        for (int j = 0; j < KNN_; j++) { tv[j] = -INFINITY; ti[j] = -1; }
        #pragma unroll
        for (int k = 0; k < 32; k++) {
            float x = v[k];
            if (x > tv[KNN_ - 1]) {
                int p = KNN_ - 1;
                while (p > 0 && x > tv[p - 1]) { tv[p] = tv[p - 1]; ti[p] = ti[p - 1]; p--; }
                tv[p] = x; ti[p] = seg * 32 + k;
            }
        }

        float m_ = mt, s_ = st_;
        #pragma unroll
        for (int o = 1; o <= 2; o <<= 1) {
            float mo = __shfl_xor_sync(0xffffffffu, m_, o);
            float so = __shfl_xor_sync(0xffffffffu, s_, o);
            float mm = fmaxf(m_, mo);
            float a  = (s_ > 0.f) ? s_ * __expf(m_ - mm) : 0.f;
            float b2 = (so > 0.f) ? so * __expf(mo - mm) : 0.f;
            m_ = mm; s_ = a + b2;
        }

        #pragma unroll
        for (int j = 0; j < KNN_; j++) { tvv[tid][j] = tv[j]; tii[tid][j] = ti[j]; }
        __syncwarp();

        if (seg == 0) {
            int p[4] = {0, 0, 0, 0};
            float otv[KNN_]; int oti[KNN_];
            #pragma unroll
            for (int r = 0; r < KNN_; r++) {
                float bv = -INFINITY; int bs = -1;
                #pragma unroll
                for (int q = 0; q < 4; q++) {
                    if (p[q] < KNN_) {
                        float cv_ = tvv[tid + q][p[q]];
                        if (cv_ > bv) { bv = cv_; bs = q; }
                    }
                }
                otv[r] = bv;
                oti[r] = (bs >= 0) ? c0 + tii[tid + bs][p[bs]] : -1;
                if (bs >= 0) p[bs]++;
            }
            const int o = n * NTILE + bt;
            g_pm[o] = m_;
            g_ps[o] = s_;
            #pragma unroll
            for (int j = 0; j < KNN_; j++) { g_tv6[o * KNN_ + j] = otv[j]; g_ti6[o * KNN_ + j] = oti[j]; }

            const int y = lab[n];
            if (y >= c0 && y < c0 + BM)
                g_vlab[n] = (LT0[n * LDE + (y - c0)] + LT1[n * LDE + (y - c0)]) * 20.0f;
        }
    }
    __syncthreads();

    // ---------------- fused EMA update for owned label rows ----------------
    bool any = false;
    for (int b = 0; b < B_; b++)
        if (lab[b] >= c0 && lab[b] < c0 + BM) { any = true; break; }
    if (!any) return;

    const float alpha = 0.01f * (float)epoch_p[0];
    const int lane = tid & 31;

    for (int b = 0; b < B_; b++) {
        const int y = lab[b];
        if (y < c0 || y >= c0 + BM) continue;
        bool head = true;
        for (int j = 0; j < b; j++)
            if (lab[j] == y) { head = false; break; }
        if (!head) continue;

        float r[4];
        #pragma unroll
        for (int k = 0; k < 4; k++) r[k] = Em[(long long)y * D_ + k * NTHR + tid];

        for (int i = b; i < B_; i++) {
            if (lab[i] != y) continue;
            float sq = 0.f;
            #pragma unroll
            for (int k = 0; k < 4; k++) {
                r[k] = alpha * r[k] + (1.f - alpha) * X[i * D_ + k * NTHR + tid];
                sq = fmaf(r[k], r[k], sq);
            }
            #pragma unroll
            for (int o = 16; o > 0; o >>= 1) sq += __shfl_xor_sync(0xffffffffu, sq, o);
            if (lane == 0) red[wid] = sq;
            __syncthreads();
            if (tid == 0) {
                float tot = 0.f;
                #pragma unroll
                for (int w = 0; w < 16; w++) tot += red[w];
                red[16] = tot;
            }
            __syncthreads();
            float inv = rsqrtf(red[16]);
            __syncthreads();
            #pragma unroll
            for (int k = 0; k < 4; k++) r[k] *= inv;
        }

        #pragma unroll
        for (int k = 0; k < 4; k++) out1[(long long)y * D_ + k * NTHR + tid] = r[k];
    }
}

// ---------------------------------------------------------------------------
// Combine v2 (R11-verbatim): one block (128 thr) per batch row.
// ---------------------------------------------------------------------------
__global__ __launch_bounds__(128) void combine_kernel(const int* __restrict__ label,
                                                      float* __restrict__ loss_out) {
    const int tid  = threadIdx.x;
    const int lane = tid & 31;
    const int wrp  = tid >> 5;
    const int b    = blockIdx.x;

    float m = -INFINITY, s = 0.f;
    float tv[KNN_]; int ti[KNN_];
    #pragma unroll
    for (int j = 0; j < KNN_; j++) { tv[j] = -INFINITY; ti[j] = -1; }

    for (int t = tid; t < NTILE; t += 128) {
        const int o = b * NTILE + t;
        float mo = g_pm[o], so = g_ps[o];
        float mm = fmaxf(m, mo);
        float a  = (s  > 0.f) ? s  * __expf(m  - mm) : 0.f;
        float c2 = (so > 0.f) ? so * __expf(mo - mm) : 0.f;
        m = mm; s = a + c2;
        #pragma unroll
        for (int j = 0; j < KNN_; j++) {
            float x = g_tv6[o * KNN_ + j];
            if (x > tv[KNN_ - 1]) {
                int xi = g_ti6[o * KNN_ + j];
                int p = KNN_ - 1;
                while (p > 0 && x > tv[p - 1]) { tv[p] = tv[p - 1]; ti[p] = ti[p - 1]; p--; }
                tv[p] = x; ti[p] = xi;
            } else break;
        }
    }

    #pragma unroll
    for (int o = 16; o > 0; o >>= 1) {
        float mo = __shfl_xor_sync(0xffffffffu, m, o);
        float so = __shfl_xor_sync(0xffffffffu, s, o);
        float mm = fmaxf(m, mo);
        float a  = (s  > 0.f) ? s  * __expf(m  - mm) : 0.f;
        float c2 = (so > 0.f) ? so * __expf(mo - mm) : 0.f;
        m = mm; s = a + c2;
    }

    float wtv[KNN_]; int wti[KNN_];
    {
        int p = 0;
        #pragma unroll
        for (int r = 0; r < KNN_; r++) {
            float cand = (p < KNN_) ? tv[p] : -INFINITY;
            int   cidx = (p < KNN_) ? ti[p] : -1;
            float bv = cand; int bl = lane;
            #pragma unroll
            for (int o = 16; o > 0; o >>= 1) {
                float ov = __shfl_xor_sync(0xffffffffu, bv, o);
                int   ol = __shfl_xor_sync(0xffffffffu, bl, o);
                if (ov > bv || (ov == bv && ol < bl)) { bv = ov; bl = ol; }
            }
            int widx = __shfl_sync(0xffffffffu, cidx, bl);
            if (lane == bl) p++;
            wtv[r] = bv; wti[r] = widx;
        }
    }

    __shared__ float smm[4], sms[4];
    __shared__ float swv[4][KNN_];
    __shared__ int   swi[4][KNN_];
    if (lane == 0) { smm[wrp] = m; sms[wrp] = s; }
    if (lane < KNN_) { swv[wrp][lane] = wtv[lane]; swi[wrp][lane] = wti[lane]; }
    __syncthreads();

    if (wrp == 0) {
        float fm = smm[0], fs = sms[0];
        #pragma unroll
        for (int w = 1; w < 4; w++) {
            float mo = smm[w], so = sms[w];
            float mm2 = fmaxf(fm, mo);
            float a  = (fs > 0.f) ? fs * __expf(fm - mm2) : 0.f;
            float c2 = (so > 0.f) ? so * __expf(mo - mm2) : 0.f;
            fm = mm2; fs = a + c2;
        }
        const float LSE = fm + logf(fs);

        float cand = (lane < 24) ? swv[lane / KNN_][lane % KNN_] : -INFINITY;
        int   cidx = (lane < 24) ? swi[lane / KNN_][lane % KNN_] : -1;

        const int y = label[b];
        float sum6 = 0.f;
        int   in = 0;
        #pragma unroll
        for (int r = 0; r < KNN_; r++) {
            float bv = cand; int bl = lane;
            #pragma unroll
            for (int o = 16; o > 0; o >>= 1) {
                float ov = __shfl_xor_sync(0xffffffffu, bv, o);
                int   ol = __shfl_xor_sync(0xffffffffu, bl, o);
                if (ov > bv || (ov == bv && ol < bl)) { bv = ov; bl = ol; }
            }
            int widx = __shfl_sync(0xffffffffu, cidx, bl);
            if (lane == bl) cand = -INFINITY;
            sum6 += (LSE - bv);
            if (widx == y) in = 1;
        }

        if (lane == 0) {
            float ll = LSE - g_vlab[b];
            g_rowloss[b] = 2.f * sum6 + (3.f - 2.f * (float)in) * ll;
        }
    }

    __shared__ int is_last;
    __syncthreads();
    if (tid == 0) {
        __threadfence();
        is_last = (atomicAdd(&g_done, 1) == B_ - 1);
    }
    __syncthreads();
    if (is_last && tid < 32) {
        float accv = 0.f;
        #pragma unroll
        for (int k = 0; k < 4; k++) accv += g_rowloss[tid + k * 32];
        #pragma unroll
        for (int o = 16; o > 0; o >>= 1) accv += __shfl_xor_sync(0xffffffffu, accv, o);
        if (tid == 0) {
            loss_out[0] = accv / (float)B_;
            g_done = 0;
        }
    }
}

// ---------------------------------------------------------------------------
// Launch (R11 schedule — no streams)
// ---------------------------------------------------------------------------
extern "C" void kernel_launch(void* const* d_in, const int* in_sizes, int n_in,
                              void* d_out, int out_size) {
    const float* X     = (const float*)d_in[0];  // [128, 2048] f32
    const int*   label = (const int*)  d_in[1];  // [128] i32
    const float* Em    = (const float*)d_in[2];  // [16522, 2048] f32
    const int*   epoch = (const int*)  d_in[3];  // scalar

    float* out = (float*)d_out;                  // [0]=loss, [1..]=em_new

    cudaFuncSetAttribute(gemm_fused, cudaFuncAttributeMaxDynamicSharedMemorySize, SMEM_DYN);

    gemm_fused    <<<NTILE, NTHR, SMEM_DYN>>>(X, Em, label, epoch, out + 1);
    combine_kernel<<<B_, 128>>>(label, out);
}